// round 5
// baseline (speedup 1.0000x reference)
#include <cuda_runtime.h>
#include <cuda_fp16.h>
#include <cstdint>
#include <math.h>

#define N_NODES 50000
#define N_EDGES 625000
#define N_GRAPHS 256
#define CH 128
#define N_OUT 10

// ---------------- scratch (no allocations allowed) ----------------
__device__ __half g_xh[N_NODES * CH];
__device__ __half g_z [N_NODES * CH];
__device__ __half g_t1[N_NODES * CH];
__device__ __half g_t2[N_NODES * CH];
__device__ __half g_h [N_NODES * CH];
__device__ __half g_Wh[9 * CH * CH];   // fp16, transposed [n][k]

__device__ int   g_deg   [N_NODES];
__device__ int   g_cursor[N_NODES];
__device__ int   g_rowptr[N_NODES + 1];
__device__ int   g_csrsrc[N_EDGES];
__device__ int   g_bsums [64];

__device__ float g_pooled[N_GRAPHS * CH];
__device__ float g_counts[N_GRAPHS];

// ---------------- utility ----------------
__global__ void zero_deg_cursor(int* deg, int* cursor) {
    int i = blockIdx.x * blockDim.x + threadIdx.x;
    if (i < N_NODES) { deg[i] = 0; cursor[i] = 0; }
}
__global__ void zero_pool(float* pooled, float* counts) {
    int i = blockIdx.x * blockDim.x + threadIdx.x;
    if (i < N_GRAPHS * CH) pooled[i] = 0.0f;
    if (i < N_GRAPHS) counts[i] = 0.0f;
}

// x (fp32) -> fp16, vectorized
__global__ void xh_prep(const float* __restrict__ x, __half* __restrict__ xh) {
    int i = blockIdx.x * blockDim.x + threadIdx.x;   // float4 index
    if (i >= (N_NODES * CH) / 4) return;
    float4 v = *(const float4*)(x + i * 4);
    __half2 h0 = __floats2half2_rn(v.x, v.y);
    __half2 h1 = __floats2half2_rn(v.z, v.w);
    uint2 o;
    o.x = *(uint32_t*)&h0;
    o.y = *(uint32_t*)&h1;
    *(uint2*)(xh + i * 4) = o;
}

// ---------------- W transpose + fp16 convert (once per launch) -------------
__global__ void wh_prep(const float* __restrict__ W, __half* __restrict__ Wh) {
    __shared__ float tile[32][33];
    int g = blockIdx.z;
    int tx = threadIdx.x, ty = threadIdx.y;
    int kt = blockIdx.x * 32, nt = blockIdx.y * 32;
    const float* Wg = W + g * CH * CH;
    __half* Whg = Wh + g * CH * CH;
#pragma unroll
    for (int i = 0; i < 32; i += 8)
        tile[ty + i][tx] = Wg[(kt + ty + i) * CH + nt + tx];
    __syncthreads();
#pragma unroll
    for (int i = 0; i < 32; i += 8)
        Whg[(nt + ty + i) * CH + kt + tx] = __float2half_rn(tile[tx][ty + i]);
}

// ---------------- CSR build ----------------
__global__ void count_deg(const int* __restrict__ dst, int* __restrict__ deg) {
    int e = blockIdx.x * blockDim.x + threadIdx.x;
    if (e < N_EDGES) atomicAdd(&deg[dst[e]], 1);
}

__global__ void scan_blocks(const int* __restrict__ deg, int* __restrict__ rowptr,
                            int* __restrict__ bsums) {
    __shared__ int wsum[32];
    int gid = blockIdx.x * 1024 + threadIdx.x;
    int v = (gid < N_NODES) ? deg[gid] : 0;
    int lane = threadIdx.x & 31, wid = threadIdx.x >> 5;
    int x = v;
#pragma unroll
    for (int o = 1; o < 32; o <<= 1) {
        int y = __shfl_up_sync(0xffffffffu, x, o);
        if (lane >= o) x += y;
    }
    if (lane == 31) wsum[wid] = x;
    __syncthreads();
    if (wid == 0) {
        int s = wsum[lane];
#pragma unroll
        for (int o = 1; o < 32; o <<= 1) {
            int y = __shfl_up_sync(0xffffffffu, s, o);
            if (lane >= o) s += y;
        }
        wsum[lane] = s;
    }
    __syncthreads();
    int base = (wid > 0) ? wsum[wid - 1] : 0;
    int incl = base + x;
    if (gid < N_NODES) rowptr[gid] = incl - v;
    if (threadIdx.x == 1023) bsums[blockIdx.x] = incl;
}

__global__ void add_boff(int* __restrict__ rowptr, const int* __restrict__ bsums, int nblocks) {
    __shared__ int pre;
    if (threadIdx.x == 0) {
        int run = 0;
        for (int i = 0; i < (int)blockIdx.x; i++) run += bsums[i];
        pre = run;
        if ((int)blockIdx.x == nblocks - 1)
            rowptr[N_NODES] = run + bsums[nblocks - 1];
    }
    __syncthreads();
    int gid = blockIdx.x * 1024 + threadIdx.x;
    if (gid < N_NODES) rowptr[gid] += pre;
}

__global__ void scatter_edges(const int* __restrict__ src, const int* __restrict__ dst,
                              const int* __restrict__ rowptr, int* __restrict__ cursor,
                              int* __restrict__ csrsrc) {
    int e = blockIdx.x * blockDim.x + threadIdx.x;
    if (e >= N_EDGES) return;
    int d = dst[e];
    int slot = rowptr[d] + atomicAdd(&cursor[d], 1);
    csrsrc[slot] = src[e];
}

// ---------------- aggregation (fp16 in/out, fp32 accum) --------------------
// one warp per node; lane handles 4 channels (8 bytes)
__global__ void agg_kernel(const __half* __restrict__ h, __half* __restrict__ z,
                           const int* __restrict__ rowptr, const int* __restrict__ csrsrc) {
    int warp = (blockIdx.x * blockDim.x + threadIdx.x) >> 5;
    int lane = threadIdx.x & 31;
    if (warp >= N_NODES) return;
    const uint2* hv = (const uint2*)h;   // 4 halves per element
    uint2 s = hv[warp * 32 + lane];
    float2 a0 = __half22float2(*(__half2*)&s.x);
    float2 a1 = __half22float2(*(__half2*)&s.y);
    int beg = rowptr[warp], end = rowptr[warp + 1];
    for (int i = beg; i < end; i++) {
        int src = csrsrc[i];
        uint2 w = hv[src * 32 + lane];
        float2 v0 = __half22float2(*(__half2*)&w.x);
        float2 v1 = __half22float2(*(__half2*)&w.y);
        a0.x += v0.x; a0.y += v0.y; a1.x += v1.x; a1.y += v1.y;
    }
    __half2 o0 = __floats2half2_rn(a0.x, a0.y);
    __half2 o1 = __floats2half2_rn(a1.x, a1.y);
    uint2 o;
    o.x = *(uint32_t*)&o0;
    o.y = *(uint32_t*)&o1;
    ((uint2*)z)[warp * 32 + lane] = o;
}

// ---------------- fp16 tensor-core GEMM (mma.sync m16n8k16, ldmatrix) ------
// C[M,128] = A[M,128] @ Wh^T + bias (opt relu); A, C fp16; Wh is [n][k] fp16.
// CTA tile 128x128, K=128 full. 8 warps: 4(M) x 2(N), warp = 32x64.
#define HS 136
#define GEMM_SMEM (2 * 128 * HS * 2)   // 69632 B

__device__ __forceinline__ void mma16816(float* d, uint32_t a0, uint32_t a1,
                                         uint32_t a2, uint32_t a3,
                                         uint32_t b0, uint32_t b1) {
    asm volatile(
        "mma.sync.aligned.m16n8k16.row.col.f32.f16.f16.f32 "
        "{%0,%1,%2,%3}, {%4,%5,%6,%7}, {%8,%9}, {%0,%1,%2,%3};"
        : "+f"(d[0]), "+f"(d[1]), "+f"(d[2]), "+f"(d[3])
        : "r"(a0), "r"(a1), "r"(a2), "r"(a3), "r"(b0), "r"(b1));
}

__device__ __forceinline__ void ldsm_x4(uint32_t& r0, uint32_t& r1, uint32_t& r2,
                                        uint32_t& r3, uint32_t addr) {
    asm volatile("ldmatrix.sync.aligned.m8n8.x4.shared.b16 {%0,%1,%2,%3}, [%4];"
        : "=r"(r0), "=r"(r1), "=r"(r2), "=r"(r3) : "r"(addr));
}

__global__ __launch_bounds__(256, 2) void gemm_fp16(
    const __half* __restrict__ A, const __half* __restrict__ Wh,
    const float* __restrict__ bias, __half* __restrict__ C,
    int M, int relu)
{
    extern __shared__ __align__(16) char smem[];
    __half* Ash = (__half*)smem;             // [128][HS]
    __half* Bsh = Ash + 128 * HS;            // [128][HS]

    int tid = threadIdx.x;
    int row0 = blockIdx.x * 128;

    // stage A (fp16, uint4 = 8 halves): 128 rows x 16 chunks
#pragma unroll
    for (int it = 0; it < 8; it++) {
        int q = tid + it * 256;          // 0..2047
        int r = q >> 4;                  // row
        int k8 = q & 15;                 // 8-half chunk
        uint4 v = make_uint4(0u, 0u, 0u, 0u);
        int gr = row0 + r;
        if (gr < M) v = *(const uint4*)(A + (size_t)gr * 128 + k8 * 8);
        *(uint4*)(Ash + r * HS + k8 * 8) = v;
    }
#pragma unroll
    for (int it = 0; it < 8; it++) {
        int q = tid + it * 256;
        int n = q >> 4;
        int k8 = q & 15;
        uint4 w = *(const uint4*)(Wh + (size_t)n * 128 + k8 * 8);
        *(uint4*)(Bsh + n * HS + k8 * 8) = w;
    }
    __syncthreads();

    int lane = tid & 31, w = tid >> 5;
    int wm = w & 3, wn = w >> 2;           // 4 x 2 warp grid
    int m0 = wm * 32, n0 = wn * 64;
    int grp = lane >> 2, tig = lane & 3;

    // ldmatrix smem byte addresses
    uint32_t aBase = (uint32_t)__cvta_generic_to_shared(Ash);
    uint32_t bBase = (uint32_t)__cvta_generic_to_shared(Bsh);
    uint32_t aAddr[2], bAddr[4];
#pragma unroll
    for (int mt = 0; mt < 2; mt++)
        aAddr[mt] = aBase + (((m0 + mt * 16 + (lane & 15)) * HS + (lane >> 4) * 8) << 1);
#pragma unroll
    for (int jj = 0; jj < 4; jj++)
        bAddr[jj] = bBase + (((n0 + jj * 16 + (lane & 7) + ((lane >> 4) << 3)) * HS +
                              ((lane >> 3) & 1) * 8) << 1);

    float acc[2][8][4];
#pragma unroll
    for (int mt = 0; mt < 2; mt++)
#pragma unroll
        for (int j = 0; j < 8; j++)
#pragma unroll
            for (int i = 0; i < 4; i++) acc[mt][j][i] = 0.0f;

#pragma unroll
    for (int ks = 0; ks < 8; ks++) {
        uint32_t af[2][4];
#pragma unroll
        for (int mt = 0; mt < 2; mt++)
            ldsm_x4(af[mt][0], af[mt][1], af[mt][2], af[mt][3], aAddr[mt] + ks * 32);
#pragma unroll
        for (int jj = 0; jj < 4; jj++) {
            uint32_t b0, b1, b2, b3;
            ldsm_x4(b0, b1, b2, b3, bAddr[jj] + ks * 32);
            mma16816(acc[0][jj * 2],     af[0][0], af[0][1], af[0][2], af[0][3], b0, b1);
            mma16816(acc[1][jj * 2],     af[1][0], af[1][1], af[1][2], af[1][3], b0, b1);
            mma16816(acc[0][jj * 2 + 1], af[0][0], af[0][1], af[0][2], af[0][3], b2, b3);
            mma16816(acc[1][jj * 2 + 1], af[1][0], af[1][1], af[1][2], af[1][3], b2, b3);
        }
    }

    // epilogue: fp16 output
#pragma unroll
    for (int mt = 0; mt < 2; mt++) {
        int r = row0 + m0 + mt * 16 + grp;
#pragma unroll
        for (int j = 0; j < 8; j++) {
            int c = n0 + j * 8 + tig * 2;
            float bx = __ldg(bias + c), by = __ldg(bias + c + 1);
            if (r < M) {
                float v0 = acc[mt][j][0] + bx, v1 = acc[mt][j][1] + by;
                if (relu) { v0 = fmaxf(v0, 0.f); v1 = fmaxf(v1, 0.f); }
                *(__half2*)(C + (size_t)r * 128 + c) = __floats2half2_rn(v0, v1);
            }
            if (r + 8 < M) {
                float v2 = acc[mt][j][2] + bx, v3 = acc[mt][j][3] + by;
                if (relu) { v2 = fmaxf(v2, 0.f); v3 = fmaxf(v3, 0.f); }
                *(__half2*)(C + (size_t)(r + 8) * 128 + c) = __floats2half2_rn(v2, v3);
            }
        }
    }
}

// ---------------- pooling scatter (fp16 in, fp32 atomics) ------------------
__global__ void pool_kernel(const __half* __restrict__ h, const int* __restrict__ gid,
                            float* __restrict__ pooled, float* __restrict__ counts) {
    int warp = (blockIdx.x * blockDim.x + threadIdx.x) >> 5;
    int lane = threadIdx.x & 31;
    if (warp >= N_NODES) return;
    int g = gid[warp];
    uint2 v = ((const uint2*)h)[warp * 32 + lane];
    float2 v0 = __half22float2(*(__half2*)&v.x);
    float2 v1 = __half22float2(*(__half2*)&v.y);
    float* base = pooled + g * 128 + lane * 4;
    atomicAdd(base + 0, v0.x);
    atomicAdd(base + 1, v0.y);
    atomicAdd(base + 2, v1.x);
    atomicAdd(base + 3, v1.y);
    if (lane == 0) atomicAdd(&counts[g], 1.0f);
}

// ---------------- head ----------------
__global__ void head_kernel(const float* __restrict__ pooled, const float* __restrict__ counts,
                            const float* __restrict__ W1, const float* __restrict__ b1,
                            const float* __restrict__ W2, const float* __restrict__ b2,
                            float* __restrict__ out) {
    int g = blockIdx.x;
    int t = threadIdx.x;
    __shared__ float p[128];
    __shared__ float h1[128];
    __shared__ float logits[N_OUT];

    float cnt = fmaxf(counts[g], 1.0f);
    p[t] = pooled[g * 128 + t] / cnt;
    __syncthreads();

    float acc = b1[t];
#pragma unroll 8
    for (int k = 0; k < 128; k++) acc += p[k] * W1[k * 128 + t];
    h1[t] = fmaxf(acc, 0.0f);
    __syncthreads();

    if (t < N_OUT) {
        float a = b2[t];
#pragma unroll 8
        for (int k = 0; k < 128; k++) a += h1[k] * W2[k * N_OUT + t];
        logits[t] = a;
    }
    __syncthreads();

    if (t == 0) {
        float m = -1e30f;
#pragma unroll
        for (int o = 0; o < N_OUT; o++) m = fmaxf(m, logits[o]);
        float e[N_OUT], s = 0.0f;
#pragma unroll
        for (int o = 0; o < N_OUT; o++) { e[o] = __expf(logits[o] - m); s += e[o]; }
        float inv = 1.0f / s;
#pragma unroll
        for (int o = 0; o < N_OUT; o++) out[g * N_OUT + o] = e[o] * inv;
    }
}

// ---------------- launch ----------------
extern "C" void kernel_launch(void* const* d_in, const int* in_sizes, int n_in,
                              void* d_out, int out_size) {
    const float* x        = (const float*)d_in[0];
    const int*   edge_src = (const int*)  d_in[1];
    const int*   edge_dst = (const int*)  d_in[2];
    const int*   graph_id = (const int*)  d_in[3];
    const float* conv_W   = (const float*)d_in[4];
    const float* conv_b   = (const float*)d_in[5];
    const float* d1_W     = (const float*)d_in[6];
    const float* d1_b     = (const float*)d_in[7];
    const float* d2_W     = (const float*)d_in[8];
    const float* d2_b     = (const float*)d_in[9];
    float* out = (float*)d_out;

    __half *xh, *z, *t1, *t2, *h, *Wh;
    float *pooled, *counts;
    int *deg, *cursor, *rowptr, *csrsrc, *bsums;
    cudaGetSymbolAddress((void**)&xh,     g_xh);
    cudaGetSymbolAddress((void**)&z,      g_z);
    cudaGetSymbolAddress((void**)&t1,     g_t1);
    cudaGetSymbolAddress((void**)&t2,     g_t2);
    cudaGetSymbolAddress((void**)&h,      g_h);
    cudaGetSymbolAddress((void**)&Wh,     g_Wh);
    cudaGetSymbolAddress((void**)&pooled, g_pooled);
    cudaGetSymbolAddress((void**)&counts, g_counts);
    cudaGetSymbolAddress((void**)&deg,    g_deg);
    cudaGetSymbolAddress((void**)&cursor, g_cursor);
    cudaGetSymbolAddress((void**)&rowptr, g_rowptr);
    cudaGetSymbolAddress((void**)&csrsrc, g_csrsrc);
    cudaGetSymbolAddress((void**)&bsums,  g_bsums);

    cudaFuncSetAttribute(gemm_fp16, cudaFuncAttributeMaxDynamicSharedMemorySize, GEMM_SMEM);

    const int TB = 256;
    const int scanBlocks = (N_NODES + 1023) / 1024;  // 49

    // ---- prep (independent) + CSR build ----
    wh_prep<<<dim3(4, 4, 9), dim3(32, 8)>>>(conv_W, Wh);
    xh_prep<<<(N_NODES * CH / 4 + TB - 1) / TB, TB>>>(x, xh);
    zero_deg_cursor<<<(N_NODES + TB - 1) / TB, TB>>>(deg, cursor);
    count_deg<<<(N_EDGES + TB - 1) / TB, TB>>>(edge_dst, deg);
    scan_blocks<<<scanBlocks, 1024>>>(deg, rowptr, bsums);
    add_boff<<<scanBlocks, 1024>>>(rowptr, bsums, scanBlocks);
    scatter_edges<<<(N_EDGES + TB - 1) / TB, TB>>>(edge_src, edge_dst, rowptr, cursor, csrsrc);

    const int aggBlocks  = (N_NODES * 32 + TB - 1) / TB;
    const int gemmBlocks = (N_NODES + 127) / 128;   // 391

    const __half* hin = xh;
    for (int l = 0; l < 3; l++) {
        const __half* Wh0 = Wh + (size_t)(l * 3 + 0) * CH * CH;
        const __half* Wh1 = Wh + (size_t)(l * 3 + 1) * CH * CH;
        const __half* Wh2 = Wh + (size_t)(l * 3 + 2) * CH * CH;
        const float* b0  = conv_b + (size_t)(l * 3 + 0) * CH;
        const float* b1p = conv_b + (size_t)(l * 3 + 1) * CH;
        const float* b2p = conv_b + (size_t)(l * 3 + 2) * CH;

        agg_kernel<<<aggBlocks, TB>>>(hin, z, rowptr, csrsrc);
        gemm_fp16<<<gemmBlocks, 256, GEMM_SMEM>>>(z,  Wh0, b0,  t1, N_NODES, 1);
        gemm_fp16<<<gemmBlocks, 256, GEMM_SMEM>>>(t1, Wh1, b1p, t2, N_NODES, 1);
        gemm_fp16<<<gemmBlocks, 256, GEMM_SMEM>>>(t2, Wh2, b2p, h,  N_NODES, 0);
        hin = h;
    }

    zero_pool<<<(N_GRAPHS * CH + TB - 1) / TB, TB>>>(pooled, counts);
    pool_kernel<<<aggBlocks, TB>>>(h, graph_id, pooled, counts);
    head_kernel<<<N_GRAPHS, 128>>>(pooled, counts, d1_W, d1_b, d2_W, d2_b, out);
}